// round 4
// baseline (speedup 1.0000x reference)
#include <cuda_runtime.h>

#define BB 512
#define TT 512
#define IN_DIM 256
#define NJ 32          // 4 gates * 8 qubits
#define DTOT 264
#define ROWS (BB*TT)

// scratch: input projection [B*T][32]
__device__ float g_proj[(size_t)ROWS * NJ];

typedef unsigned long long ull;

__device__ __forceinline__ ull pack2(float lo, float hi) {
    ull r;
    asm("mov.b64 %0, {%1, %2};" : "=l"(r) : "r"(__float_as_uint(lo)), "r"(__float_as_uint(hi)));
    return r;
}
__device__ __forceinline__ ull fma2(ull a, ull b, ull c) {
    ull d;
    asm("fma.rn.f32x2 %0, %1, %2, %3;" : "=l"(d) : "l"(a), "l"(b), "l"(c));
    return d;
}

#define KC 16

// proj[r][j] = sum_k x[r][k] * W_g[q][k],  j = g*8+q
__global__ void __launch_bounds__(128) gemm_kernel(
    const float* __restrict__ x,
    const float* __restrict__ Wf, const float* __restrict__ Wi,
    const float* __restrict__ Wg, const float* __restrict__ Wo)
{
    __shared__ __align__(16) float ws[IN_DIM * NJ];   // [k][j], 32 KB
    __shared__ float xs[128 * 17];                    // 128 rows x 16 k, pad 17
    const int tid = threadIdx.x;

    for (int e = tid; e < IN_DIM * NJ; e += 128) {
        int k = e >> 5, j = e & 31;
        const float* Wp = (j < 8) ? Wf : (j < 16) ? Wi : (j < 24) ? Wg : Wo;
        ws[e] = Wp[(j & 7) * DTOT + k];
    }

    const int row0 = blockIdx.x * 128;
    const float* xrow_base = x + (size_t)row0 * IN_DIM;

    ull acc[16];
    #pragma unroll
    for (int p = 0; p < 16; p++) acc[p] = 0ull;

    __syncthreads();

    for (int k0 = 0; k0 < IN_DIM; k0 += KC) {
        #pragma unroll
        for (int i = 0; i < KC; i++) {   // 128*KC elems / 128 threads
            int e = i * 128 + tid;
            int r = e >> 4, k = e & 15;
            xs[r * 17 + k] = xrow_base[(size_t)r * IN_DIM + k0 + k];
        }
        __syncthreads();
        #pragma unroll
        for (int k = 0; k < KC; k++) {
            float xv = xs[tid * 17 + k];
            ull xp = pack2(xv, xv);
            const double2* wv = reinterpret_cast<const double2*>(ws + (k0 + k) * NJ);
            #pragma unroll
            for (int p4 = 0; p4 < 8; p4++) {
                double2 w = wv[p4];
                acc[2*p4]   = fma2(xp, (ull)__double_as_longlong(w.x), acc[2*p4]);
                acc[2*p4+1] = fma2(xp, (ull)__double_as_longlong(w.y), acc[2*p4+1]);
            }
        }
        __syncthreads();
    }

    double2* outv = reinterpret_cast<double2*>(g_proj + (size_t)(row0 + tid) * NJ);
    #pragma unroll
    for (int p4 = 0; p4 < 8; p4++) {
        double2 o;
        o.x = __longlong_as_double((long long)acc[2*p4]);
        o.y = __longlong_as_double((long long)acc[2*p4+1]);
        outv[p4] = o;
    }
}

// one warp per batch element; lane j = gate (j>>3), qubit (j&7)
__global__ void __launch_bounds__(128) recur_kernel(
    const float* __restrict__ Wf, const float* __restrict__ bf,
    const float* __restrict__ Wi, const float* __restrict__ bi,
    const float* __restrict__ Wg, const float* __restrict__ bg,
    const float* __restrict__ Wo, const float* __restrict__ bo,
    const float* __restrict__ thetas, float* __restrict__ out)
{
    const unsigned FULL = 0xffffffffu;
    const int wg   = (blockIdx.x * blockDim.x + threadIdx.x) >> 5;  // batch index
    const int lane = threadIdx.x & 31;
    const int g = lane >> 3, q = lane & 7;

    const float* Wp = (g == 0) ? Wf : (g == 1) ? Wi : (g == 2) ? Wg : Wo;
    const float* bp = (g == 0) ? bf : (g == 1) ? bi : (g == 2) ? bg : bo;

    float wh[8];
    #pragma unroll
    for (int k = 0; k < 8; k++) wh[k] = Wp[q * DTOT + IN_DIM + k];
    const float bt = bp[q] + thetas[g * 8 + q];

    const float* pr = g_proj + (size_t)wg * TT * NJ + lane;
    float p0 = __ldg(pr);
    float p1 = __ldg(pr + NJ);

    float hx = 0.f, cx = 0.f;
    float* outp = out + (size_t)wg * TT * 8 + q;

    for (int t = 0; t < TT; t++) {
        float pin = p0;
        p0 = p1;
        int tn = t + 2; if (tn > TT - 1) tn = TT - 1;
        p1 = __ldg(pr + (size_t)tn * NJ);

        // ang_j = proj + bias + thetas + Wh_j . hx
        float ang = pin + bt;
        #pragma unroll
        for (int k = 0; k < 8; k++)
            ang = fmaf(wh[k], __shfl_sync(FULL, hx, k), ang);

        // quantum circuit -> Z expectations (analytic)
        float c = __cosf(ang);
        float p = c;                               // inclusive prefix product within 8-lane group
        #pragma unroll
        for (int d = 1; d < 8; d <<= 1) {
            float v = __shfl_up_sync(FULL, p, d, 8);
            if (q >= d) p *= v;
        }
        float r = (q == 0) ? 1.0f : c;             // product of c over lanes 1..7 of group
        r *= __shfl_xor_sync(FULL, r, 1);
        r *= __shfl_xor_sync(FULL, r, 2);
        r *= __shfl_xor_sync(FULL, r, 4);
        float m = (q == 0) ? r : p;

        // branch-free activation: sigmoid for gates 0,1,3; tanh for gate 2
        float km = (g == 2) ? (-2.0f * m) : (-m);
        float e  = __expf(km);
        float u  = __fdividef(1.0f, 1.0f + e);
        u = (g == 2) ? (2.0f * u - 1.0f) : u;

        float f_ = __shfl_sync(FULL, u, q);
        float i_ = __shfl_sync(FULL, u, q + 8);
        float g_ = __shfl_sync(FULL, u, q + 16);
        float o_ = __shfl_sync(FULL, u, q + 24);

        cx = fmaf(f_, cx, i_ * g_);
        float e2 = __expf(-2.0f * cx);
        float th = __fdividef(2.0f, 1.0f + e2) - 1.0f;
        hx = o_ * th;

        if (lane < 8) outp[(size_t)t * 8] = hx;
    }

    if (lane < 8) {
        out[(size_t)BB * TT * 8 + (size_t)wg * 8 + q] = hx;                      // final hx
        out[(size_t)BB * TT * 8 + (size_t)BB * 8 + (size_t)wg * 8 + q] = cx;     // final cx
    }
}

extern "C" void kernel_launch(void* const* d_in, const int* in_sizes, int n_in,
                              void* d_out, int out_size) {
    (void)in_sizes; (void)n_in; (void)out_size;
    const float* x  = (const float*)d_in[0];
    const float* Wf = (const float*)d_in[1]; const float* bf = (const float*)d_in[2];
    const float* Wi = (const float*)d_in[3]; const float* bi = (const float*)d_in[4];
    const float* Wg = (const float*)d_in[5]; const float* bg = (const float*)d_in[6];
    const float* Wo = (const float*)d_in[7]; const float* bo = (const float*)d_in[8];
    const float* th = (const float*)d_in[9];
    float* out = (float*)d_out;

    gemm_kernel<<<ROWS / 128, 128>>>(x, Wf, Wi, Wg, Wo);
    recur_kernel<<<(BB * 32) / 128, 128>>>(Wf, bf, Wi, bi, Wg, bg, Wo, bo, th, out);
}

// round 5
// speedup vs baseline: 1.0214x; 1.0214x over previous
#include <cuda_runtime.h>

#define BB 512
#define TT 512
#define IN_DIM 256
#define NJ 32          // 4 gates * 8 qubits
#define DTOT 264
#define ROWS (BB*TT)

// scratch: input projection, layout [row][q*4+g]  (q = qubit, g = gate f,i,g,o)
__device__ float g_proj[(size_t)ROWS * NJ];

typedef unsigned long long ull;

__device__ __forceinline__ ull pack2(float lo, float hi) {
    ull r;
    asm("mov.b64 %0, {%1, %2};" : "=l"(r) : "r"(__float_as_uint(lo)), "r"(__float_as_uint(hi)));
    return r;
}
__device__ __forceinline__ ull fma2(ull a, ull b, ull c) {
    ull d;
    asm("fma.rn.f32x2 %0, %1, %2, %3;" : "=l"(d) : "l"(a), "l"(b), "l"(c));
    return d;
}

#define GR 512   // rows per block
#define KC 4     // k tile

// proj[r][q*4+g] = sum_k x[r][k] * W_g[q][k]
__global__ void __launch_bounds__(128) gemm_kernel(
    const float* __restrict__ x,
    const float* __restrict__ Wf, const float* __restrict__ Wi,
    const float* __restrict__ Wg, const float* __restrict__ Wo)
{
    __shared__ __align__(16) float ws[IN_DIM * NJ];     // [k][q*4+g], 32 KB
    __shared__ float xs[GR * (KC + 1)];                 // 512 rows x 4 k, pad 5 -> 10 KB
    const int tid = threadIdx.x;

    for (int e = tid; e < IN_DIM * NJ; e += 128) {
        int k = e >> 5, j = e & 31;
        int q = j >> 2, g = j & 3;
        const float* Wp = (g == 0) ? Wf : (g == 1) ? Wi : (g == 2) ? Wg : Wo;
        ws[e] = Wp[q * DTOT + k];
    }

    const int row0 = blockIdx.x * GR;

    ull acc[64];
    #pragma unroll
    for (int p = 0; p < 64; p++) acc[p] = 0ull;

    __syncthreads();

    for (int k0 = 0; k0 < IN_DIM; k0 += KC) {
        // stage 512 rows x 4 k (one float4 per row)
        #pragma unroll
        for (int i = 0; i < 4; i++) {
            int r = i * 128 + tid;
            float4 v = *reinterpret_cast<const float4*>(x + (size_t)(row0 + r) * IN_DIM + k0);
            xs[r * 5 + 0] = v.x; xs[r * 5 + 1] = v.y;
            xs[r * 5 + 2] = v.z; xs[r * 5 + 3] = v.w;
        }
        __syncthreads();
        #pragma unroll
        for (int k = 0; k < KC; k++) {
            const double2* wv = reinterpret_cast<const double2*>(ws + (k0 + k) * NJ);
            ull w[16];
            #pragma unroll
            for (int p4 = 0; p4 < 8; p4++) {
                double2 wd = wv[p4];
                w[2*p4]   = (ull)__double_as_longlong(wd.x);
                w[2*p4+1] = (ull)__double_as_longlong(wd.y);
            }
            #pragma unroll
            for (int ri = 0; ri < 4; ri++) {
                float xv = xs[(tid + ri * 128) * 5 + k];
                ull xp = pack2(xv, xv);
                #pragma unroll
                for (int p = 0; p < 16; p++)
                    acc[ri * 16 + p] = fma2(xp, w[p], acc[ri * 16 + p]);
            }
        }
        __syncthreads();
    }

    #pragma unroll
    for (int ri = 0; ri < 4; ri++) {
        int row = row0 + tid + ri * 128;
        double2* outv = reinterpret_cast<double2*>(g_proj + (size_t)row * NJ);
        #pragma unroll
        for (int p4 = 0; p4 < 8; p4++) {
            double2 o;
            o.x = __longlong_as_double((long long)acc[ri * 16 + 2*p4]);
            o.y = __longlong_as_double((long long)acc[ri * 16 + 2*p4 + 1]);
            outv[p4] = o;
        }
    }
}

// one warp per 4 batch elements; lane = (sub batch)*8 + qubit; all 4 gates local to lane
__global__ void __launch_bounds__(32) recur_kernel(
    const float* __restrict__ Wf, const float* __restrict__ bf,
    const float* __restrict__ Wi, const float* __restrict__ bi,
    const float* __restrict__ Wg, const float* __restrict__ bg,
    const float* __restrict__ Wo, const float* __restrict__ bo,
    const float* __restrict__ thetas, float* __restrict__ out)
{
    const unsigned FULL = 0xffffffffu;
    const int lane = threadIdx.x;
    const int q = lane & 7;
    const int wg = blockIdx.x * 4 + (lane >> 3);   // batch index

    const float* Wptr[4] = {Wf, Wi, Wg, Wo};
    const float* bptr[4] = {bf, bi, bg, bo};

    float wh[4][8];
    float bt[4];
    #pragma unroll
    for (int g = 0; g < 4; g++) {
        #pragma unroll
        for (int k = 0; k < 8; k++) wh[g][k] = Wptr[g][q * DTOT + IN_DIM + k];
        bt[g] = bptr[g][q] + thetas[g * 8 + q];
    }

    const float4* pr = reinterpret_cast<const float4*>(g_proj + (size_t)wg * TT * NJ) + q;
    // stride per t = 8 float4
    float4 p0 = pr[0];
    float4 p1 = pr[8];

    float hx = 0.f, cx = 0.f;
    float* outp = out + (size_t)wg * TT * 8 + q;

    for (int t = 0; t < TT; t++) {
        float4 pin = p0;
        p0 = p1;
        int tn = t + 2; if (tn > TT - 1) tn = TT - 1;
        p1 = pr[(size_t)tn * 8];

        // broadcast hidden state (hoisted, independent shuffles)
        float hxv[8];
        #pragma unroll
        for (int k = 0; k < 8; k++) hxv[k] = __shfl_sync(FULL, hx, k, 8);

        float ang[4];
        ang[0] = pin.x + bt[0]; ang[1] = pin.y + bt[1];
        ang[2] = pin.z + bt[2]; ang[3] = pin.w + bt[3];
        #pragma unroll
        for (int g = 0; g < 4; g++) {
            float s0 = fmaf(wh[g][0], hxv[0], fmaf(wh[g][2], hxv[2],
                       fmaf(wh[g][4], hxv[4], wh[g][6] * hxv[6])));
            float s1 = fmaf(wh[g][1], hxv[1], fmaf(wh[g][3], hxv[3],
                       fmaf(wh[g][5], hxv[5], wh[g][7] * hxv[7])));
            ang[g] += s0 + s1;
        }

        // analytic circuit: m_k = prod_{0..k} cos, m_0 = prod_{1..7} cos
        float cth[4], p[4];
        #pragma unroll
        for (int g = 0; g < 4; g++) {
            cth[g] = __cosf(ang[g]);
            p[g] = (q == 0) ? 1.0f : cth[g];       // lane0 contributes identity
        }
        #pragma unroll
        for (int d = 1; d < 8; d <<= 1) {
            #pragma unroll
            for (int g = 0; g < 4; g++) {
                float v = __shfl_up_sync(FULL, p[g], d, 8);
                if (q >= d) p[g] *= v;
            }
        }
        float m[4];
        #pragma unroll
        for (int g = 0; g < 4; g++) {
            float m7 = __shfl_sync(FULL, p[g], 7, 8);    // prod_{1..7} c
            float c0 = __shfl_sync(FULL, cth[g], 0, 8);  // c_0
            m[g] = (q == 0) ? m7 : c0 * p[g];
        }

        // gates (all lane-local)
        float f_ = __fdividef(1.0f, 1.0f + __expf(-m[0]));
        float i_ = __fdividef(1.0f, 1.0f + __expf(-m[1]));
        float gg = __fdividef(2.0f, 1.0f + __expf(-2.0f * m[2])) - 1.0f;
        float o_ = __fdividef(1.0f, 1.0f + __expf(-m[3]));

        cx = fmaf(f_, cx, i_ * gg);
        float th = __fdividef(2.0f, 1.0f + __expf(-2.0f * cx)) - 1.0f;
        hx = o_ * th;

        outp[(size_t)t * 8] = hx;
    }

    out[(size_t)BB * TT * 8 + (size_t)wg * 8 + q] = hx;                        // final hx
    out[(size_t)BB * TT * 8 + (size_t)BB * 8 + (size_t)wg * 8 + q] = cx;       // final cx
}

extern "C" void kernel_launch(void* const* d_in, const int* in_sizes, int n_in,
                              void* d_out, int out_size) {
    (void)in_sizes; (void)n_in; (void)out_size;
    const float* x  = (const float*)d_in[0];
    const float* Wf = (const float*)d_in[1]; const float* bf = (const float*)d_in[2];
    const float* Wi = (const float*)d_in[3]; const float* bi = (const float*)d_in[4];
    const float* Wg = (const float*)d_in[5]; const float* bg = (const float*)d_in[6];
    const float* Wo = (const float*)d_in[7]; const float* bo = (const float*)d_in[8];
    const float* th = (const float*)d_in[9];
    float* out = (float*)d_out;

    gemm_kernel<<<ROWS / GR, 128>>>(x, Wf, Wi, Wg, Wo);
    recur_kernel<<<BB / 4, 32>>>(Wf, bf, Wi, bi, Wg, bg, Wo, bo, th, out);
}